// round 7
// baseline (speedup 1.0000x reference)
#include <cuda_runtime.h>
#include <cuda_bf16.h>

// QueryAndGroup fused, v5.
// v4 main kernel (37.5us): L1=57% driven by 32-way-scattered feature gather
// (~512 L1 wavefronts/warp) and an O(H) ranking pass (~760 issue slots/warp).
// v5:
//  - bitmap ranking: hits set bits in a per-warp 512-word smem bitmap; walk in
//    index order with popc+warp-scan extracts the first 32 (exact, no CAP).
//  - staged gather: 2 samples x 32 channels per LDG.64 (2 lines/instr) ->
//    smem stage -> coalesced stores. Gather wavefronts 512 -> ~64.
//  - bitmap and stage share one union'd smem buffer (disjoint lifetimes).
//  - per-row x-range pruning via sqrt(r^2 - dymin^2 - dzmin^2).

#define BQ_B 2
#define BQ_N 16384
#define BQ_P 4096
#define BQ_C 64
#define BQ_S 32
// f32 rounding of python double 0.1*0.1. Do NOT use 0.1f*0.1f (1 ulp higher).
#define BQ_R2 0.01f
#define BQ_R  0.1f

#define GRID_DIM 10
#define NCELL   (GRID_DIM * GRID_DIM * GRID_DIM)   // 1000
#define TOTCELL (BQ_B * NCELL)                      // 2000
#define WPB  8
#define NWORD 512                                   // BQ_N/32 bitmap words
#define STRIDE 34                                   // stage row stride (floats)

#define TR_BLOCKS (BQ_B * (BQ_C / 32) * (BQ_N / 32))   // 2048
#define PK_BLOCKS ((BQ_B * BQ_N + 1023) / 1024)        // 32

// Scratch (__device__ globals). g_cellCount re-zeroed by main kernel tail.
__device__ float4 g_xyz4[BQ_B * BQ_N];
__device__ __align__(16) float g_featT[BQ_B * BQ_N * BQ_C];  // (B,N,C)
__device__ float4 g_xyzSorted[BQ_B * BQ_N];                  // cell-sorted, w=idx
__device__ int g_cellOf[BQ_B * BQ_N];                        // cell | rank<<11
__device__ int g_cellCount[TOTCELL];
__device__ int g_cellStart[TOTCELL + 1];

__device__ __forceinline__ int cell_coord(float x) {
    int c = (int)(x * (float)GRID_DIM);
    return min(max(c, 0), GRID_DIM - 1);
}

// ---- prep 1 (fused): feature transpose (B,C,N)->(B,N,C) + xyz pack/hist ----
__global__ __launch_bounds__(1024)
void prep_kernel(const float* __restrict__ xyz, const float* __restrict__ feat) {
    if (blockIdx.x < TR_BLOCKS) {
        __shared__ float tile[32][33];
        const int bid = blockIdx.x;
        const int n0 = (bid & 511) * 32;
        const int c0 = ((bid >> 9) & 1) * 32;
        const int b  = bid >> 10;
        const int tx = threadIdx.x & 31, ty = threadIdx.x >> 5;
        tile[ty][tx] = feat[((size_t)b * BQ_C + c0 + ty) * BQ_N + n0 + tx];
        __syncthreads();
        g_featT[((size_t)b * BQ_N + n0 + ty) * BQ_C + c0 + tx] = tile[tx][ty];
    } else {
        const int i = (blockIdx.x - TR_BLOCKS) * 1024 + threadIdx.x;
        if (i < BQ_B * BQ_N) {
            const float x = xyz[3 * i + 0];
            const float y = xyz[3 * i + 1];
            const float z = xyz[3 * i + 2];
            g_xyz4[i] = make_float4(x, y, z, 0.f);
            const int b = i >> 14;
            const int cell = b * NCELL +
                (cell_coord(z) * GRID_DIM + cell_coord(y)) * GRID_DIM + cell_coord(x);
            const int rank = atomicAdd(&g_cellCount[cell], 1);
            g_cellOf[i] = cell | (rank << 11);   // cell < 2048
        }
    }
}

// ---- prep 2: exclusive scan over 2000 counts (1 block, shfl warp-scan) ----
__global__ __launch_bounds__(1024)
void scan_kernel() {
    __shared__ int warpsum[32];
    const int t = threadIdx.x;
    const int lane = t & 31, w = t >> 5;
    const int x0 = (2 * t < TOTCELL)     ? g_cellCount[2 * t]     : 0;
    const int x1 = (2 * t + 1 < TOTCELL) ? g_cellCount[2 * t + 1] : 0;
    const int s = x0 + x1;
    int incl = s;
#pragma unroll
    for (int d = 1; d < 32; d <<= 1) {
        const int v = __shfl_up_sync(0xffffffffu, incl, d);
        if (lane >= d) incl += v;
    }
    if (lane == 31) warpsum[w] = incl;
    __syncthreads();
    if (w == 0) {
        const int ws = warpsum[lane];
        int wincl = ws;
#pragma unroll
        for (int d = 1; d < 32; d <<= 1) {
            const int v = __shfl_up_sync(0xffffffffu, wincl, d);
            if (lane >= d) wincl += v;
        }
        warpsum[lane] = wincl - ws;
    }
    __syncthreads();
    const int off = warpsum[w] + incl - s;
    if (2 * t < TOTCELL) {
        g_cellStart[2 * t]     = off;
        g_cellStart[2 * t + 1] = off + x0;
    }
    if (2 * t == TOTCELL) g_cellStart[TOTCELL] = off;  // sentinel = B*N
}

// ---- prep 3: scatter (atomic-free: rank precomputed in cellOf) ----
__global__ __launch_bounds__(128)
void scatter_kernel() {
    const int i = blockIdx.x * 128 + threadIdx.x;
    if (i >= BQ_B * BQ_N) return;
    const int packed = g_cellOf[i];
    const int cell = packed & 2047;
    const int rank = packed >> 11;
    float4 p = g_xyz4[i];
    p.w = __int_as_float(i & (BQ_N - 1));
    g_xyzSorted[g_cellStart[cell] + rank] = p;
}

// ---- main: grid ball query + group (one warp per query) ----
struct __align__(16) WarpBuf {
    union {
        unsigned bm[NWORD];          // 2048 B  (phase A: hit bitmap)
        float stage[32 * STRIDE];    // 4352 B  (phase B: feature staging)
    };
};

__global__ __launch_bounds__(WPB * 32)
void query_and_group_kernel(const float* __restrict__ new_xyz,
                            float* __restrict__ out) {
    __shared__ WarpBuf s_buf[WPB];
    __shared__ int s_idx[WPB][BQ_S];

    const int warp = threadIdx.x >> 5;
    const int lane = threadIdx.x & 31;
    const int gwarp = blockIdx.x * WPB + warp;
    const int b = gwarp >> 12;
    const int p = gwarp & (BQ_P - 1);

    // zero this warp's bitmap (16 words/lane = 4x STS.128)
    {
        uint4* bm4 = (uint4*)s_buf[warp].bm;
#pragma unroll
        for (int t = 0; t < 4; ++t)
            bm4[t * 32 + lane] = make_uint4(0, 0, 0, 0);
    }
    __syncwarp();

    const float4* __restrict__ xb4 = g_xyz4 + (size_t)b * BQ_N;
    const size_t qoff = ((size_t)b * BQ_P + p) * 3;
    const float qx = new_xyz[qoff + 0];
    const float qy = new_xyz[qoff + 1];
    const float qz = new_xyz[qoff + 2];

    const int cy0 = max(0, (int)floorf((qy - BQ_R) * 10.f - 1e-3f));
    const int cy1 = min(GRID_DIM - 1, (int)floorf((qy + BQ_R) * 10.f + 1e-3f));
    const int cz0 = max(0, (int)floorf((qz - BQ_R) * 10.f - 1e-3f));
    const int cz1 = min(GRID_DIM - 1, (int)floorf((qz + BQ_R) * 10.f + 1e-3f));

    const int* __restrict__ cs = g_cellStart + b * NCELL;

    // ---- Phase 1: scan; hits set bits (exact index-order recovery later) ----
    for (int cz = cz0; cz <= cz1; ++cz) {
        const float dzmin = fmaxf(0.f, fmaxf(cz * 0.1f - qz, qz - (cz + 1) * 0.1f));
        for (int cy = cy0; cy <= cy1; ++cy) {
            const float dymin = fmaxf(0.f, fmaxf(cy * 0.1f - qy, qy - (cy + 1) * 0.1f));
            const float rem = BQ_R2 + 1e-6f - dzmin * dzmin - dymin * dymin;
            if (rem < 0.f) continue;               // row can't contain hits
            const float w = sqrtf(rem);            // per-row x half-width
            const int rx0 = max(0, (int)floorf((qx - w) * 10.f - 1e-3f));
            const int rx1 = min(GRID_DIM - 1, (int)floorf((qx + w) * 10.f + 1e-3f));
            const int rb = (cz * GRID_DIM + cy) * GRID_DIM;
            const int beg = __ldg(&cs[rb + rx0]);
            const int end = __ldg(&cs[rb + rx1 + 1]);   // contiguous x-run
            for (int i0 = beg; i0 < end; i0 += 32) {
                const int i = i0 + lane;
                if (i < end) {
                    const float4 pt = g_xyzSorted[i];
                    const float dx = pt.x - qx;
                    const float dy = pt.y - qy;
                    const float dz = pt.z - qz;
                    if (dx * dx + dy * dy + dz * dz < BQ_R2) {
                        const int v = __float_as_int(pt.w);
                        atomicOr(&s_buf[warp].bm[v >> 5], 1u << (v & 31));
                    }
                }
            }
        }
    }
    __syncwarp();

    // ---- Bitmap walk: first BQ_S set bits in index order ----
    int total = 0;
    for (int t = 0; t < NWORD / 32 && total < BQ_S; ++t) {
        const unsigned wv = s_buf[warp].bm[t * 32 + lane];
        const int c = __popc(wv);
        int incl = c;
#pragma unroll
        for (int d = 1; d < 32; d <<= 1) {
            const int v = __shfl_up_sync(0xffffffffu, incl, d);
            if (lane >= d) incl += v;
        }
        int r = total + incl - c;                 // rank base for this word
        unsigned ww = wv;
        while (ww && r < BQ_S) {
            const int bpos = __ffs(ww) - 1;
            s_idx[warp][r] = (t * 32 + lane) * 32 + bpos;
            ww &= ww - 1;
            ++r;
        }
        total += __shfl_sync(0xffffffffu, incl, 31);
    }
    __syncwarp();
    const int first = (total > 0) ? s_idx[warp][0] : 0;  // min-index hit
    if (lane >= total) s_idx[warp][lane] = first;        // pad (no-op if >=32)
    __syncwarp();

    const int my = s_idx[warp][lane];

    // ---- Phase 2a: grouped_xyz ----
    const size_t chstride = (size_t)BQ_P * BQ_S;
    const size_t obase = (((size_t)b * (3 + BQ_C)) * BQ_P + p) * BQ_S + lane;

    const float4 pm = xb4[my];
    out[obase]                = pm.x - qx;
    out[obase + chstride]     = pm.y - qy;
    out[obase + 2 * chstride] = pm.z - qz;
    const size_t ofeat = obase + 3 * chstride;

    // ---- Phase 2b: staged feature gather ----
    // load: 2 samples x 32 channels per LDG.64 (exactly 2x128B lines/instr)
    const float* __restrict__ fb = g_featT + (size_t)b * BQ_N * BQ_C;
    for (int ch = 0; ch < 2; ++ch) {
        const int c0 = ch * 32;
        __syncwarp();   // stage reuse (and bitmap retirement on first pass)
#pragma unroll
        for (int i = 0; i < 16; ++i) {
            const int s  = 2 * i + (lane >> 4);
            const int m  = s_idx[warp][s];         // 2-way LDS broadcast
            const int c2 = (lane & 15) * 2;
            const float2 v = *reinterpret_cast<const float2*>(
                fb + (size_t)m * BQ_C + c0 + c2);
            *reinterpret_cast<float2*>(&s_buf[warp].stage[s * STRIDE + c2]) = v;
        }
        __syncwarp();
#pragma unroll
        for (int c = 0; c < 32; ++c) {
            out[ofeat + (size_t)(c0 + c) * chstride] =
                s_buf[warp].stage[lane * STRIDE + c];
        }
    }

    // Re-zero cell counters for the next invocation (replaces zero kernel).
    if (blockIdx.x < 8) {
        const int i = blockIdx.x * 256 + threadIdx.x;
        if (i < TOTCELL) g_cellCount[i] = 0;
    }
}

extern "C" void kernel_launch(void* const* d_in, const int* in_sizes, int n_in,
                              void* d_out, int out_size) {
    const float* xyz     = (const float*)d_in[0];
    const float* new_xyz = (const float*)d_in[1];
    const float* feat    = (const float*)d_in[2];
    float* out = (float*)d_out;

    prep_kernel<<<TR_BLOCKS + PK_BLOCKS, 1024>>>(xyz, feat);
    scan_kernel<<<1, 1024>>>();
    scatter_kernel<<<(BQ_B * BQ_N + 127) / 128, 128>>>();

    const int grid = (BQ_B * BQ_P) / WPB;   // 1024
    query_and_group_kernel<<<grid, WPB * 32>>>(new_xyz, out);
}